// round 6
// baseline (speedup 1.0000x reference)
#include <cuda_runtime.h>

// out[k] = sum_d x[d] * S[d][k],  S[d][k] = sum_n M[n][d][k].
// M flattened to 400 float4 rows (row p = (n,d), comps = k).
//
// 2 warps / 64 threads: halves the per-warp LDG issue span (LSU floor 4
// cyc/LDG) that sits in front of the exposed L2 latency (L1 is flushed per
// launch on Blackwell, so replays are L2-bound). Thread g owns rows
// p = g + 64j; 64 % 4 == 0 so d = g & 3 is fixed per thread and the x scalar
// is loop-invariant. 400 = 64*6 + 16: 6 unconditional loads + tail (g<16).
//
// x is decoupled: accumulation is pure FADDs, x's L2 load overlaps it; one
// FMUL per component applies x[d]. Reduction: transposed smem dump
// (conflict-free padded rows) + __syncthreads (BAR floor 7) + 4 reader lanes
// each summing one 64-float component row (16x LDS.128, tree depth 4+2).

__global__ void __launch_bounds__(64, 1)
bigfanout_kernel(const float* __restrict__ x,
                 const float* __restrict__ matrices,
                 float* __restrict__ out) {
    // Row stride 68 floats (272 B, 16B-aligned): STS conflict-free per row,
    // reader lanes start on distinct banks.
    __shared__ __align__(16) float sm[4 * 68];

    const int g = threadIdx.x;            // 0..63
    const float xv = x[g & 3];            // issued early; consumed late

    const float4* __restrict__ rows = reinterpret_cast<const float4*>(matrices);

    // Pure-add accumulation, dual accumulators (chain 3 + merge).
    float e0 = 0.f, e1 = 0.f, e2 = 0.f, e3 = 0.f;
    float o0 = 0.f, o1 = 0.f, o2 = 0.f, o3 = 0.f;

    #pragma unroll
    for (int j = 0; j < 6; j += 2) {
        float4 re = rows[g + 64 * j];
        float4 ro = rows[g + 64 * (j + 1)];
        e0 += re.x;  e1 += re.y;  e2 += re.z;  e3 += re.w;
        o0 += ro.x;  o1 += ro.y;  o2 += ro.z;  o3 += ro.w;
    }

    // Tail: rows 384..399, threads 0..15. 384 % 4 == 0 so d = g&3 holds.
    if (g < 16) {
        float4 r = rows[384 + g];
        e0 += r.x;  e1 += r.y;  e2 += r.z;  e3 += r.w;
    }

    // Apply x[d] (first consumer of the x load); dump transposed:
    // smem row k holds the 64 thread-partials of out[k].
    sm[0 * 68 + g] = (e0 + o0) * xv;
    sm[1 * 68 + g] = (e1 + o1) * xv;
    sm[2 * 68 + g] = (e2 + o2) * xv;
    sm[3 * 68 + g] = (e3 + o3) * xv;

    __syncthreads();

    // Threads 0..3: sum component row g (64 floats = 16x LDS.128).
    if (g < 4) {
        const float4* r4 = reinterpret_cast<const float4*>(&sm[g * 68]);
        float4 acc0, acc1, acc2, acc3;
        {
            float4 a = r4[0], b = r4[1], c = r4[2], d = r4[3];
            acc0.x = a.x + b.x;  acc0.y = a.y + b.y;  acc0.z = a.z + b.z;  acc0.w = a.w + b.w;
            acc1.x = c.x + d.x;  acc1.y = c.y + d.y;  acc1.z = c.z + d.z;  acc1.w = c.w + d.w;
        }
        {
            float4 a = r4[4], b = r4[5], c = r4[6], d = r4[7];
            acc2.x = a.x + b.x;  acc2.y = a.y + b.y;  acc2.z = a.z + b.z;  acc2.w = a.w + b.w;
            acc3.x = c.x + d.x;  acc3.y = c.y + d.y;  acc3.z = c.z + d.z;  acc3.w = c.w + d.w;
        }
        float4 acc4, acc5, acc6, acc7;
        {
            float4 a = r4[8], b = r4[9], c = r4[10], d = r4[11];
            acc4.x = a.x + b.x;  acc4.y = a.y + b.y;  acc4.z = a.z + b.z;  acc4.w = a.w + b.w;
            acc5.x = c.x + d.x;  acc5.y = c.y + d.y;  acc5.z = c.z + d.z;  acc5.w = c.w + d.w;
        }
        {
            float4 a = r4[12], b = r4[13], c = r4[14], d = r4[15];
            acc6.x = a.x + b.x;  acc6.y = a.y + b.y;  acc6.z = a.z + b.z;  acc6.w = a.w + b.w;
            acc7.x = c.x + d.x;  acc7.y = c.y + d.y;  acc7.z = c.z + d.z;  acc7.w = c.w + d.w;
        }
        // Tree-merge 8 float4 accumulators (depth 3) + horizontal (depth 2).
        acc0.x += acc1.x;  acc0.y += acc1.y;  acc0.z += acc1.z;  acc0.w += acc1.w;
        acc2.x += acc3.x;  acc2.y += acc3.y;  acc2.z += acc3.z;  acc2.w += acc3.w;
        acc4.x += acc5.x;  acc4.y += acc5.y;  acc4.z += acc5.z;  acc4.w += acc5.w;
        acc6.x += acc7.x;  acc6.y += acc7.y;  acc6.z += acc7.z;  acc6.w += acc7.w;
        acc0.x += acc2.x;  acc0.y += acc2.y;  acc0.z += acc2.z;  acc0.w += acc2.w;
        acc4.x += acc6.x;  acc4.y += acc6.y;  acc4.z += acc6.z;  acc4.w += acc6.w;
        acc0.x += acc4.x;  acc0.y += acc4.y;  acc0.z += acc4.z;  acc0.w += acc4.w;

        out[g] = (acc0.x + acc0.y) + (acc0.z + acc0.w);
    }
}

extern "C" void kernel_launch(void* const* d_in, const int* in_sizes, int n_in,
                              void* d_out, int out_size) {
    const float* x        = (const float*)d_in[0];   // [1,4] float32
    const float* matrices = (const float*)d_in[1];   // [100,4,4] float32
    float* out            = (float*)d_out;           // [4] float32

    bigfanout_kernel<<<1, 64>>>(x, matrices, out);
}